// round 6
// baseline (speedup 1.0000x reference)
#include <cuda_runtime.h>
#include <math.h>
#include <stdint.h>

typedef unsigned long long u64;

// ---------------- scratch (device globals; no allocation allowed) ----------
__device__ float g_xg  [16u*2048u*512u];   // precomputed input gates [B,S,4H]
__device__ float g_lstm[16u*2048u*128u];   // lstm hidden states [B,S,H]
__device__ float g_ctx [16u*2048u*128u];   // attention context [B,S,H]
__device__ float g_ha  [32768u*132u];      // MLP ping buffer (stride 132)
__device__ float g_hb  [32768u*132u];      // MLP pong buffer

__device__ __forceinline__ float sigf(float x) {
    return __fdividef(1.f, 1.f + __expf(-x));
}
__device__ __forceinline__ float tanh_fast(float x) {
    return fmaf(2.f, sigf(2.f * x), -1.f);
}

// packed f32x2 helpers ------------------------------------------------------
__device__ __forceinline__ void fma2(u64& c, u64 a, u64 b) {
    asm("fma.rn.f32x2 %0, %1, %2, %0;" : "+l"(c) : "l"(a), "l"(b));
}
__device__ __forceinline__ float2 upk(u64 v) {
    unsigned lo, hi;
    asm("mov.b64 {%0, %1}, %2;" : "=r"(lo), "=r"(hi) : "l"(v));
    return make_float2(__uint_as_float(lo), __uint_as_float(hi));
}
__device__ __forceinline__ float hsum2(u64 v) { float2 f = upk(v); return f.x + f.y; }

// tf32 helpers ---------------------------------------------------------------
__device__ __forceinline__ unsigned tf32of(float f) {
    unsigned u; asm("cvt.rna.tf32.f32 %0, %1;" : "=r"(u) : "f"(f)); return u;
}
__device__ __forceinline__ void mma_tf32(float* c, const unsigned* a,
                                         unsigned b0, unsigned b1) {
    asm volatile(
        "mma.sync.aligned.m16n8k8.row.col.f32.tf32.tf32.f32 "
        "{%0,%1,%2,%3}, {%4,%5,%6,%7}, {%8,%9}, {%0,%1,%2,%3};"
        : "+f"(c[0]), "+f"(c[1]), "+f"(c[2]), "+f"(c[3])
        : "r"(a[0]), "r"(a[1]), "r"(a[2]), "r"(a[3]), "r"(b0), "r"(b1));
}

__global__ void k_nop() {}

// ---------------- K1: xg = x @ W_ih^T + b_ih  ([32768,129]@[129,512]) ------
__global__ void k_xg(const float* __restrict__ x,
                     const float* __restrict__ Wih,
                     const float* __restrict__ bih) {
    extern __shared__ float sm[];
    float* xs = sm;            // [64][132]
    float* ws = sm + 64 * 132; // [64][132]
    const int m0 = blockIdx.x * 64;
    const int g0 = blockIdx.y * 64;
    const int tid = threadIdx.x;

    for (int i = tid; i < 64 * 132; i += 256) {
        int r = i / 132, c = i - r * 132;
        xs[i] = (c < 129) ? x[(size_t)(m0 + r) * 129 + c] : 0.f;
    }
    for (int i = tid; i < 64 * 132; i += 256) {
        int r = i / 132, c = i - r * 132;
        ws[i] = (c < 129) ? Wih[(size_t)(g0 + r) * 129 + c] : 0.f;
    }
    __syncthreads();

    const int ty = tid >> 4, tx = tid & 15;
    u64 acc2[4][4] = {};
    const ulonglong2* xs2 = (const ulonglong2*)xs;
    const ulonglong2* ws2 = (const ulonglong2*)ws;

#pragma unroll 3
    for (int k = 0; k < 33; k++) {
        ulonglong2 xv[4], wv[4];
#pragma unroll
        for (int i = 0; i < 4; i++) xv[i] = xs2[(4 * ty + i) * 33 + k];
#pragma unroll
        for (int j = 0; j < 4; j++) wv[j] = ws2[(4 * tx + j) * 33 + k];
#pragma unroll
        for (int i = 0; i < 4; i++)
#pragma unroll
            for (int j = 0; j < 4; j++) {
                fma2(acc2[i][j], xv[i].x, wv[j].x);
                fma2(acc2[i][j], xv[i].y, wv[j].y);
            }
    }

#pragma unroll
    for (int i = 0; i < 4; i++)
#pragma unroll
        for (int j = 0; j < 4; j++) {
            int g = g0 + 4 * tx + j;
            g_xg[(size_t)(m0 + 4 * ty + i) * 512 + g] = hsum2(acc2[i][j]) + bih[g];
        }
}

// ---------------- K2: LSTM, 2-CTA cluster per batch ------------------------
// 32 CTAs (cluster 2), 256 thr. Thread: gate gt=t&3 (i,f,g,o), dim jd=rank*64+(t>>2).
// All 128 weights per gate in registers. Quad-shfl combines gates; leader lane
// writes h locally + to peer CTA (st.shared::cluster); barrier.cluster per step.
__global__ void __launch_bounds__(256, 1) __cluster_dims__(2, 1, 1)
k_lstm2(const float* __restrict__ Whh, const float* __restrict__ bhh) {
    __shared__ float hb[2][128];

    const int t  = threadIdx.x;
    const int gt = t & 3;           // 0=i,1=f,2=g,3=o
    const int d  = t >> 2;          // 0..63
    const int rank = blockIdx.x & 1;
    const int b    = blockIdx.x >> 1;
    const int jd   = rank * 64 + d;
    const int row  = gt * 128 + jd; // gate row in [0,512)

    // load this gate's full weight row into registers (64 u64 = 128 floats)
    u64 w[64];
    {
        const ulonglong2* Wp = (const ulonglong2*)(Whh + (size_t)row * 128);
#pragma unroll
        for (int k = 0; k < 32; k++) { ulonglong2 v = Wp[k]; w[2*k] = v.x; w[2*k+1] = v.y; }
    }
    const float bg = bhh[row];

    if (t < 128) { hb[0][t] = 0.f; }
    float c = 0.f;

    const float* xgp = g_xg + (size_t)b * 2048 * 512 + row;
    float xgv = xgp[0];
    __syncthreads();

    const int lane = t & 31;
    const int qb   = lane & ~3;     // quad base lane
    const bool leader = (gt == 0);
    float* glout = g_lstm + (size_t)b * 2048 * 128 + jd;

    for (int s = 0; s < 2048; s++) {
        float nx = (s + 1 < 2048) ? xgp[(size_t)(s + 1) * 512] : 0.f;

        // dot(w, h) with 4 independent f32x2 accumulators
        const ulonglong2* h2 = (const ulonglong2*)hb[s & 1];
        u64 a0 = 0ull, a1 = 0ull, a2 = 0ull, a3 = 0ull;
#pragma unroll
        for (int k = 0; k < 16; k++) {
            ulonglong2 p = h2[2 * k];
            ulonglong2 q = h2[2 * k + 1];
            fma2(a0, w[4*k],   p.x); fma2(a1, w[4*k+1], p.y);
            fma2(a2, w[4*k+2], q.x); fma2(a3, w[4*k+3], q.y);
        }
        float pre = hsum2(a0) + hsum2(a1) + hsum2(a2) + hsum2(a3) + xgv + bg;

        // per-lane activation, quad shfl combine
        float act = (gt == 2) ? tanh_fast(pre) : sigf(pre);
        float fa = __shfl_sync(0xffffffffu, act, qb + 1, 32);
        float ga = __shfl_sync(0xffffffffu, act, qb + 2, 32);
        float oa = __shfl_sync(0xffffffffu, act, qb + 3, 32);

        if (leader) {
            c = fmaf(fa, c, act * ga);          // act = sig(i)
            float h = oa * tanh_fast(c);
            int nxt = (s + 1) & 1;
            hb[nxt][jd] = h;
            // write peer CTA's h buffer
            unsigned laddr = (unsigned)__cvta_generic_to_shared(&hb[nxt][jd]);
            asm volatile(
                "{ .reg .u32 ra; mapa.shared::cluster.u32 ra, %0, %1;\n\t"
                "  st.shared::cluster.f32 [ra], %2; }"
                :: "r"(laddr), "r"(rank ^ 1), "f"(h));
            glout[(size_t)s * 128] = h;
        }
        xgv = nx;

        // cluster-wide barrier: orders local+remote h stores before next reads
        asm volatile("barrier.cluster.arrive.aligned;" ::: "memory");
        asm volatile("barrier.cluster.wait.aligned;"   ::: "memory");
    }
}

// ---------------- K3: flash attention, tf32 mma.sync (lean registers) ------
__global__ void __launch_bounds__(128) k_attn() {
    extern __shared__ float sm[];
    float* qs = sm;                 // [64][132] tf32 bits of q * 1/sqrt(129)
    float* ks = sm + 64 * 132;      // [64][132] tf32 bits of K==V chunk
    float* ps = ks + 64 * 132;      // [64][68]  tf32 probs

    const int b  = blockIdx.y;
    const int r0 = blockIdx.x * 64;
    const float* base = g_lstm + (size_t)b * 2048 * 128;
    const int tid  = threadIdx.x;
    const int warp = tid >> 5, lane = tid & 31;
    const int gid  = lane >> 2, tig = lane & 3;
    const int wr   = warp * 16;
    const float rs = 0.08804509063256238f; // 1/sqrt(129)

    {   // stage q tile: scale + tf32-round
        const float4* qg = (const float4*)(base + (size_t)r0 * 128);
        float4* qs4 = (float4*)qs;
        for (int i = tid; i < 2048; i += 128) {
            int row = i >> 5, c = i & 31;
            float4 v = qg[row * 32 + c];
            v.x = __uint_as_float(tf32of(v.x * rs));
            v.y = __uint_as_float(tf32of(v.y * rs));
            v.z = __uint_as_float(tf32of(v.z * rs));
            v.w = __uint_as_float(tf32of(v.w * rs));
            qs4[row * 33 + c] = v;
        }
    }

    float m0 = -1e30f, m1 = -1e30f, l0 = 0.f, l1 = 0.f;
    float o[16][4];
#pragma unroll
    for (int n = 0; n < 16; n++) { o[n][0]=0.f; o[n][1]=0.f; o[n][2]=0.f; o[n][3]=0.f; }

    const unsigned* qsu = (const unsigned*)qs;
    const unsigned* ksu = (const unsigned*)ks;

    for (int kt = 0; kt < 32; kt++) {
        __syncthreads();  // prior phase-2 reads of ks done (also covers q stage)
        {   // stage K/V chunk as tf32
            const float4* kg = (const float4*)(base + (size_t)kt * 64 * 128);
            float4* ks4 = (float4*)ks;
            for (int i = tid; i < 2048; i += 128) {
                int row = i >> 5, c = i & 31;
                float4 v = kg[row * 32 + c];
                v.x = __uint_as_float(tf32of(v.x));
                v.y = __uint_as_float(tf32of(v.y));
                v.z = __uint_as_float(tf32of(v.z));
                v.w = __uint_as_float(tf32of(v.w));
                ks4[row * 33 + c] = v;
            }
        }
        __syncthreads();

        // phase 1: S(16x64) = Q @ K^T
        float s[8][4];
#pragma unroll
        for (int n = 0; n < 8; n++) { s[n][0]=0.f; s[n][1]=0.f; s[n][2]=0.f; s[n][3]=0.f; }
#pragma unroll
        for (int kk = 0; kk < 16; kk++) {
            unsigned a[4];
            int cc = kk * 8 + tig;
            a[0] = qsu[(wr + gid)     * 132 + cc];
            a[1] = qsu[(wr + gid + 8) * 132 + cc];
            a[2] = qsu[(wr + gid)     * 132 + cc + 4];
            a[3] = qsu[(wr + gid + 8) * 132 + cc + 4];
#pragma unroll
            for (int n = 0; n < 8; n++) {
                unsigned b0 = ksu[(n * 8 + gid) * 132 + cc];
                unsigned b1 = ksu[(n * 8 + gid) * 132 + cc + 4];
                mma_tf32(s[n], a, b0, b1);
            }
        }

        // online softmax (rows wr+gid and wr+gid+8)
        float vm0 = -1e30f, vm1 = -1e30f;
#pragma unroll
        for (int n = 0; n < 8; n++) {
            vm0 = fmaxf(vm0, fmaxf(s[n][0], s[n][1]));
            vm1 = fmaxf(vm1, fmaxf(s[n][2], s[n][3]));
        }
        vm0 = fmaxf(vm0, __shfl_xor_sync(0xffffffffu, vm0, 1));
        vm0 = fmaxf(vm0, __shfl_xor_sync(0xffffffffu, vm0, 2));
        vm1 = fmaxf(vm1, __shfl_xor_sync(0xffffffffu, vm1, 1));
        vm1 = fmaxf(vm1, __shfl_xor_sync(0xffffffffu, vm1, 2));
        float nm0 = fmaxf(m0, vm0), nm1 = fmaxf(m1, vm1);

        float sum0 = 0.f, sum1 = 0.f;
#pragma unroll
        for (int n = 0; n < 8; n++) {
            float p0 = __expf(s[n][0] - nm0);
            float p1 = __expf(s[n][1] - nm0);
            float p2 = __expf(s[n][2] - nm1);
            float p3 = __expf(s[n][3] - nm1);
            sum0 += p0 + p1; sum1 += p2 + p3;
            float* pp = ps + (wr + gid) * 68 + n * 8 + 2 * tig;
            pp[0] = __uint_as_float(tf32of(p0));
            pp[1] = __uint_as_float(tf32of(p1));
            float* pq = ps + (wr + gid + 8) * 68 + n * 8 + 2 * tig;
            pq[0] = __uint_as_float(tf32of(p2));
            pq[1] = __uint_as_float(tf32of(p3));
        }
        sum0 += __shfl_xor_sync(0xffffffffu, sum0, 1);
        sum0 += __shfl_xor_sync(0xffffffffu, sum0, 2);
        sum1 += __shfl_xor_sync(0xffffffffu, sum1, 1);
        sum1 += __shfl_xor_sync(0xffffffffu, sum1, 2);
        float alpha0 = __expf(m0 - nm0), alpha1 = __expf(m1 - nm1);
        l0 = l0 * alpha0 + sum0; m0 = nm0;
        l1 = l1 * alpha1 + sum1; m1 = nm1;
        __syncwarp();   // ps written/read within the same warp only

        // phase 2: O(16x128) += P @ V
#pragma unroll
        for (int n = 0; n < 16; n++) {
            o[n][0] *= alpha0; o[n][1] *= alpha0;
            o[n][2] *= alpha1; o[n][3] *= alpha1;
        }
        const unsigned* psu = (const unsigned*)ps;
#pragma unroll
        for (int kk = 0; kk < 8; kk++) {
            unsigned pa[4];
            pa[0] = psu[(wr + gid)     * 68 + kk * 8 + tig];
            pa[1] = psu[(wr + gid + 8) * 68 + kk * 8 + tig];
            pa[2] = psu[(wr + gid)     * 68 + kk * 8 + tig + 4];
            pa[3] = psu[(wr + gid + 8) * 68 + kk * 8 + tig + 4];
#pragma unroll
            for (int n = 0; n < 16; n++) {
                unsigned b0 = ksu[(kk * 8 + tig)     * 132 + n * 8 + gid];
                unsigned b1 = ksu[(kk * 8 + tig + 4) * 132 + n * 8 + gid];
                mma_tf32(o[n], pa, b0, b1);
            }
        }
    }

    // epilogue
    float inv0 = 1.f / l0, inv1 = 1.f / l1;
    int row0 = r0 + wr + gid, row1 = row0 + 8;
    float* d0 = g_ctx + ((size_t)b * 2048 + row0) * 128;
    float* d1 = g_ctx + ((size_t)b * 2048 + row1) * 128;
#pragma unroll
    for (int n = 0; n < 16; n++) {
        int cc = n * 8 + 2 * tig;
        *(float2*)(d0 + cc) = make_float2(o[n][0] * inv0, o[n][1] * inv0);
        *(float2*)(d1 + cc) = make_float2(o[n][2] * inv1, o[n][3] * inv1);
    }
}

// ---------------- K4: concat(context, RBF kernel feature), pad to 132 ------
__global__ void k_feat(const float* __restrict__ x, const float* __restrict__ pr) {
    const int tid = threadIdx.x;
    const int warp = tid >> 5, lane = tid & 31;
    const size_t mrow = (size_t)blockIdx.x * 8 + warp;

    const float4* c4 = (const float4*)(g_ctx + mrow * 128);
    float4* o4 = (float4*)(g_ha + mrow * 132);
    o4[lane] = c4[lane];

    const float* xr = x  + mrow * 129;
    const float* pp = pr + mrow * 129;
    float ss = 0.f;
    for (int j2 = lane; j2 < 129; j2 += 32) {
        float d = xr[j2] - pp[j2];
        ss += d * d;
    }
#pragma unroll
    for (int dd = 16; dd; dd >>= 1) ss += __shfl_xor_sync(0xffffffffu, ss, dd);
    if (lane == 0)      g_ha[mrow * 132 + 128] = __expf(-ss);
    else if (lane < 4)  g_ha[mrow * 132 + 128 + lane] = 0.f;
}

// ---------------- K5: one MLP layer h = relu(h @ Wc[l]^T + bc[l]) ----------
__global__ void k_mlp(const float* __restrict__ Wc, const float* __restrict__ bc, int l) {
    extern __shared__ float sm[];
    float* Wsh  = sm;              // [132][134]
    float* insh = sm + 132 * 134;  // [64][132]
    const float* in  = (l & 1) ? g_hb : g_ha;
    float*       out = (l & 1) ? g_ha : g_hb;

    const int m0 = blockIdx.x * 64;
    const int tid = threadIdx.x;
    const float* W  = Wc + (size_t)l * 129 * 129;
    const float* bb = bc + (size_t)l * 129;

    for (int i = tid; i < 132 * 134; i += 256) {
        int r = i / 134, c = i - r * 134;
        Wsh[i] = (r < 129 && c < 129) ? W[r * 129 + c] : 0.f;
    }
    for (int i = tid; i < 64 * 132; i += 256)
        insh[i] = in[(size_t)m0 * 132 + i];
    __syncthreads();

    const int warp = tid >> 5, lane = tid & 31;
    const int rb = warp * 8;
    const u64* W2 = (const u64*)Wsh;   // row stride 67 pairs

#pragma unroll
    for (int q = 0; q < 2; q++) {
        u64 acc2[4][5] = {};
        const int r0 = rb + 4 * q;
        const u64* h0p = (const u64*)(insh + (r0 + 0) * 132);
        const u64* h1p = (const u64*)(insh + (r0 + 1) * 132);
        const u64* h2p = (const u64*)(insh + (r0 + 2) * 132);
        const u64* h3p = (const u64*)(insh + (r0 + 3) * 132);
#pragma unroll 2
        for (int jp = 0; jp < 66; jp++) {
            u64 h0 = h0p[jp], h1 = h1p[jp], h2 = h2p[jp], h3 = h3p[jp];
#pragma unroll
            for (int cg = 0; cg < 5; cg++) {
                int cc = lane + 32 * cg;
                if (cc < 132) {
                    u64 w = W2[cc * 67 + jp];
                    fma2(acc2[0][cg], h0, w); fma2(acc2[1][cg], h1, w);
                    fma2(acc2[2][cg], h2, w); fma2(acc2[3][cg], h3, w);
                }
            }
        }
#pragma unroll
        for (int cg = 0; cg < 5; cg++) {
            int cc = lane + 32 * cg;
            if (cc < 132) {
                float bv = (cc < 129) ? bb[cc] : 0.f;
#pragma unroll
                for (int i = 0; i < 4; i++)
                    out[(size_t)(m0 + rb + 4 * q + i) * 132 + cc] =
                        fmaxf(hsum2(acc2[i][cg]) + bv, 0.f);
            }
        }
    }
}

// ---------------- K6: head + log_softmax -----------------------------------
__global__ void k_head(const float* __restrict__ Wh, const float* __restrict__ bh,
                       float* __restrict__ out) {
    const int tid = threadIdx.x;
    const int warp = tid >> 5, lane = tid & 31;
    const size_t mrow = (size_t)blockIdx.x * 8 + warp;
    const float* hr = g_ha + mrow * 132;

    float s0 = 0.f, s1 = 0.f;
    for (int j2 = lane; j2 < 129; j2 += 32) {
        float hv = hr[j2];
        s0 += hv * Wh[j2];
        s1 += hv * Wh[129 + j2];
    }
#pragma unroll
    for (int dd = 16; dd; dd >>= 1) {
        s0 += __shfl_xor_sync(0xffffffffu, s0, dd);
        s1 += __shfl_xor_sync(0xffffffffu, s1, dd);
    }
    if (lane == 0) {
        s0 += bh[0]; s1 += bh[1];
        float mx = fmaxf(s0, s1);
        float lse = mx + logf(__expf(s0 - mx) + __expf(s1 - mx));
        out[2 * mrow]     = s0 - lse;
        out[2 * mrow + 1] = s1 - lse;
    }
}

// ---------------- launch ---------------------------------------------------
extern "C" void kernel_launch(void* const* d_in, const int* in_sizes, int n_in,
                              void* d_out, int out_size) {
    const float* x     = (const float*)d_in[0];
    const float* proto = (const float*)d_in[1];
    const float* Wih   = (const float*)d_in[2];
    const float* Whh   = (const float*)d_in[3];
    const float* bih   = (const float*)d_in[4];
    const float* bhh   = (const float*)d_in[5];
    const float* Wc    = (const float*)d_in[6];
    const float* bc    = (const float*)d_in[7];
    const float* Wh    = (const float*)d_in[8];
    const float* bh    = (const float*)d_in[9];
    float* out = (float*)d_out;

    const int smem_xg   = 2 * 64 * 132 * 4;                 // 67584
    const int smem_attn = (2 * 64 * 132 + 64 * 68) * 4;     // 84992
    const int smem_mlp  = (132 * 134 + 64 * 132) * 4;       // 104544

    cudaFuncSetAttribute(k_xg,   cudaFuncAttributeMaxDynamicSharedMemorySize, smem_xg);
    cudaFuncSetAttribute(k_attn, cudaFuncAttributeMaxDynamicSharedMemorySize, smem_attn);
    cudaFuncSetAttribute(k_mlp,  cudaFuncAttributeMaxDynamicSharedMemorySize, smem_mlp);

    k_xg  <<<dim3(512, 8), 256, smem_xg>>>(x, Wih, bih);
    k_nop <<<1, 32>>>();          // shift ncu slot:
    k_nop <<<1, 32>>>();          // ... so launch #4 is k_lstm2
    k_lstm2<<<32, 256>>>(Whh, bhh);   // 16 clusters of 2 CTAs
    k_attn<<<dim3(32, 16), 128, smem_attn>>>();
    k_feat<<<4096,         256>>>(x, proto);
    for (int l = 0; l < 4; l++)
        k_mlp<<<512, 256, smem_mlp>>>(Wc, bc, l);
    k_head<<<4096, 256>>>(Wh, bh, out);
}

// round 7
// speedup vs baseline: 1.4245x; 1.4245x over previous
#include <cuda_runtime.h>
#include <math.h>
#include <stdint.h>

typedef unsigned long long u64;

// ---------------- scratch (device globals; no allocation allowed) ----------
__device__ float g_xg  [16u*2048u*512u];   // precomputed input gates [B,S,4H]
__device__ float g_lstm[16u*2048u*128u];   // lstm hidden states [B,S,H]
__device__ float g_ctx [16u*2048u*128u];   // attention context [B,S,H]
__device__ float g_ha  [32768u*132u];      // MLP ping buffer (stride 132)
__device__ float g_hb  [32768u*132u];      // MLP pong buffer

__device__ __forceinline__ float sigf(float x) {
    return __fdividef(1.f, 1.f + __expf(-x));
}
__device__ __forceinline__ float tanh_fast(float x) {
    return fmaf(2.f, sigf(2.f * x), -1.f);
}

// packed f32x2 helpers ------------------------------------------------------
__device__ __forceinline__ void fma2(u64& c, u64 a, u64 b) {
    asm("fma.rn.f32x2 %0, %1, %2, %0;" : "+l"(c) : "l"(a), "l"(b));
}
__device__ __forceinline__ float2 upk(u64 v) {
    unsigned lo, hi;
    asm("mov.b64 {%0, %1}, %2;" : "=r"(lo), "=r"(hi) : "l"(v));
    return make_float2(__uint_as_float(lo), __uint_as_float(hi));
}
__device__ __forceinline__ float hsum2(u64 v) { float2 f = upk(v); return f.x + f.y; }

// tf32 helpers ---------------------------------------------------------------
__device__ __forceinline__ unsigned tf32of(float f) {
    unsigned u; asm("cvt.rna.tf32.f32 %0, %1;" : "=r"(u) : "f"(f)); return u;
}
__device__ __forceinline__ void mma_tf32(float* c, const unsigned* a,
                                         unsigned b0, unsigned b1) {
    asm volatile(
        "mma.sync.aligned.m16n8k8.row.col.f32.tf32.tf32.f32 "
        "{%0,%1,%2,%3}, {%4,%5,%6,%7}, {%8,%9}, {%0,%1,%2,%3};"
        : "+f"(c[0]), "+f"(c[1]), "+f"(c[2]), "+f"(c[3])
        : "r"(a[0]), "r"(a[1]), "r"(a[2]), "r"(a[3]), "r"(b0), "r"(b1));
}

__global__ void k_nop() {}

// ---------------- K1: xg = x @ W_ih^T + b_ih  ([32768,129]@[129,512]) ------
__global__ void k_xg(const float* __restrict__ x,
                     const float* __restrict__ Wih,
                     const float* __restrict__ bih) {
    extern __shared__ float sm[];
    float* xs = sm;            // [64][132]
    float* ws = sm + 64 * 132; // [64][132]
    const int m0 = blockIdx.x * 64;
    const int g0 = blockIdx.y * 64;
    const int tid = threadIdx.x;

    for (int i = tid; i < 64 * 132; i += 256) {
        int r = i / 132, c = i - r * 132;
        xs[i] = (c < 129) ? x[(size_t)(m0 + r) * 129 + c] : 0.f;
    }
    for (int i = tid; i < 64 * 132; i += 256) {
        int r = i / 132, c = i - r * 132;
        ws[i] = (c < 129) ? Wih[(size_t)(g0 + r) * 129 + c] : 0.f;
    }
    __syncthreads();

    const int ty = tid >> 4, tx = tid & 15;
    u64 acc2[4][4] = {};
    const ulonglong2* xs2 = (const ulonglong2*)xs;
    const ulonglong2* ws2 = (const ulonglong2*)ws;

#pragma unroll 3
    for (int k = 0; k < 33; k++) {
        ulonglong2 xv[4], wv[4];
#pragma unroll
        for (int i = 0; i < 4; i++) xv[i] = xs2[(4 * ty + i) * 33 + k];
#pragma unroll
        for (int j = 0; j < 4; j++) wv[j] = ws2[(4 * tx + j) * 33 + k];
#pragma unroll
        for (int i = 0; i < 4; i++)
#pragma unroll
            for (int j = 0; j < 4; j++) {
                fma2(acc2[i][j], xv[i].x, wv[j].x);
                fma2(acc2[i][j], xv[i].y, wv[j].y);
            }
    }

#pragma unroll
    for (int i = 0; i < 4; i++)
#pragma unroll
        for (int j = 0; j < 4; j++) {
            int g = g0 + 4 * tx + j;
            g_xg[(size_t)(m0 + 4 * ty + i) * 512 + g] = hsum2(acc2[i][j]) + bih[g];
        }
}

// ---------------- K2: LSTM, 2-CTA cluster, mbarrier handshake --------------
// 32 CTAs (cluster 2), 256 thr. Thread: gate gt=t&3 (i,f,g,o), dim jd=rank*64+(t>>2).
// All 128 weights/gate in registers. Leaders (gt==0) write h locally + to peer
// (st.shared::cluster) and arrive.release on the PEER's mbarrier; everyone
// try_waits (acquire.cluster) on the LOCAL mbarrier. Ping-pong barriers by parity.
__global__ void __launch_bounds__(256, 1) __cluster_dims__(2, 1, 1)
k_lstm3(const float* __restrict__ Whh, const float* __restrict__ bhh) {
    __shared__ float hb[2][128];
    __shared__ alignas(16) u64 mbar[2];

    const int t  = threadIdx.x;
    const int gt = t & 3;           // 0=i,1=f,2=g,3=o
    const int d  = t >> 2;          // 0..63
    const int rank = blockIdx.x & 1;
    const int b    = blockIdx.x >> 1;
    const int jd   = rank * 64 + d;
    const int row  = gt * 128 + jd;

    // full gate weight row in registers (64 u64 = 128 floats)
    u64 w[64];
    {
        const ulonglong2* Wp = (const ulonglong2*)(Whh + (size_t)row * 128);
#pragma unroll
        for (int k = 0; k < 32; k++) { ulonglong2 v = Wp[k]; w[2*k] = v.x; w[2*k+1] = v.y; }
    }
    const float bg = bhh[row];

    if (t < 128) hb[0][t] = 0.f;
    unsigned mb_local0 = (unsigned)__cvta_generic_to_shared(&mbar[0]);
    if (t == 0) {
        asm volatile("mbarrier.init.shared.b64 [%0], 64;" :: "r"(mb_local0) : "memory");
        asm volatile("mbarrier.init.shared.b64 [%0], 64;" :: "r"(mb_local0 + 8) : "memory");
    }
    float c = 0.f;

    const float* xgp = g_xg + (size_t)b * 2048 * 512 + row;
    float xgv = xgp[0];
    __syncthreads();
    // one-time cluster sync: peer mbarrier init + hb[0] visible before any remote op
    asm volatile("barrier.cluster.arrive.aligned;" ::: "memory");
    asm volatile("barrier.cluster.wait.aligned;"   ::: "memory");

    // peer addresses (computed once)
    unsigned peer = rank ^ 1;
    unsigned hb_l = (unsigned)__cvta_generic_to_shared(&hb[0][0]);
    unsigned hb_r, mb_r;
    asm("mapa.shared::cluster.u32 %0, %1, %2;" : "=r"(hb_r) : "r"(hb_l), "r"(peer));
    asm("mapa.shared::cluster.u32 %0, %1, %2;" : "=r"(mb_r) : "r"(mb_local0), "r"(peer));

    const int lane = t & 31;
    const int qb   = lane & ~3;
    const bool leader = (gt == 0);
    float* glout = g_lstm + (size_t)b * 2048 * 128 + jd;

    for (int s = 0; s < 2048; s++) {
        float nx = (s + 1 < 2048) ? xgp[(size_t)(s + 1) * 512] : 0.f;

        const ulonglong2* h2 = (const ulonglong2*)hb[s & 1];
        u64 a0 = 0ull, a1 = 0ull, a2 = 0ull, a3 = 0ull;
#pragma unroll
        for (int k = 0; k < 16; k++) {
            ulonglong2 p = h2[2 * k];
            ulonglong2 q = h2[2 * k + 1];
            fma2(a0, w[4*k],   p.x); fma2(a1, w[4*k+1], p.y);
            fma2(a2, w[4*k+2], q.x); fma2(a3, w[4*k+3], q.y);
        }
        float pre = hsum2(a0) + hsum2(a1) + hsum2(a2) + hsum2(a3) + xgv + bg;

        float act = (gt == 2) ? tanh_fast(pre) : sigf(pre);
        float fa = __shfl_sync(0xffffffffu, act, qb + 1, 32);
        float ga = __shfl_sync(0xffffffffu, act, qb + 2, 32);
        float oa = __shfl_sync(0xffffffffu, act, qb + 3, 32);

        const int nxt = (s + 1) & 1;
        if (leader) {
            c = fmaf(fa, c, act * ga);          // act = sig(i)
            float h = oa * tanh_fast(c);
            glout[(size_t)s * 128] = h;
            if (s + 1 < 2048) {
                hb[nxt][jd] = h;
                // remote h store + release-arrive on peer's mbar[nxt]
                asm volatile("st.shared::cluster.f32 [%0], %1;"
                             :: "r"(hb_r + (unsigned)(nxt * 128 + jd) * 4u), "f"(h));
                asm volatile("mbarrier.arrive.release.cluster.shared::cluster.b64 _, [%0];"
                             :: "r"(mb_r + (unsigned)nxt * 8u) : "memory");
            }
        }
        xgv = nx;

        if (s + 1 < 2048) {
            __syncthreads();   // local h stores visible to local threads
            // wait peer's 64 arrivals on local mbar[nxt]; parity = (s>>1)&1
            unsigned mba = mb_local0 + (unsigned)nxt * 8u;
            unsigned par = (unsigned)((s >> 1) & 1);
            unsigned done;
            asm volatile(
                "{ .reg .pred p;\n\t"
                "mbarrier.try_wait.parity.acquire.cluster.shared::cta.b64 p, [%1], %2;\n\t"
                "selp.b32 %0, 1, 0, p; }"
                : "=r"(done) : "r"(mba), "r"(par) : "memory");
            if (!done) {
                asm volatile(
                    "{ .reg .pred P1;\n\t"
                    "WL_%=:\n\t"
                    "mbarrier.try_wait.parity.acquire.cluster.shared::cta.b64 P1, [%0], %1, 0x989680;\n\t"
                    "@P1 bra.uni WD_%=;\n\t"
                    "bra.uni WL_%=;\n\t"
                    "WD_%=: }"
                    :: "r"(mba), "r"(par) : "memory");
            }
        }
    }
}

// ---------------- K3: flash attention, tf32 mma.sync (lean registers) ------
__global__ void __launch_bounds__(128) k_attn() {
    extern __shared__ float sm[];
    float* qs = sm;                 // [64][132] tf32 bits of q * 1/sqrt(129)
    float* ks = sm + 64 * 132;      // [64][132] tf32 bits of K==V chunk
    float* ps = ks + 64 * 132;      // [64][68]  tf32 probs

    const int b  = blockIdx.y;
    const int r0 = blockIdx.x * 64;
    const float* base = g_lstm + (size_t)b * 2048 * 128;
    const int tid  = threadIdx.x;
    const int warp = tid >> 5, lane = tid & 31;
    const int gid  = lane >> 2, tig = lane & 3;
    const int wr   = warp * 16;
    const float rs = 0.08804509063256238f; // 1/sqrt(129)

    {   // stage q tile: scale + tf32-round
        const float4* qg = (const float4*)(base + (size_t)r0 * 128);
        float4* qs4 = (float4*)qs;
        for (int i = tid; i < 2048; i += 128) {
            int row = i >> 5, c = i & 31;
            float4 v = qg[row * 32 + c];
            v.x = __uint_as_float(tf32of(v.x * rs));
            v.y = __uint_as_float(tf32of(v.y * rs));
            v.z = __uint_as_float(tf32of(v.z * rs));
            v.w = __uint_as_float(tf32of(v.w * rs));
            qs4[row * 33 + c] = v;
        }
    }

    float m0 = -1e30f, m1 = -1e30f, l0 = 0.f, l1 = 0.f;
    float o[16][4];
#pragma unroll
    for (int n = 0; n < 16; n++) { o[n][0]=0.f; o[n][1]=0.f; o[n][2]=0.f; o[n][3]=0.f; }

    const unsigned* qsu = (const unsigned*)qs;
    const unsigned* ksu = (const unsigned*)ks;

    for (int kt = 0; kt < 32; kt++) {
        __syncthreads();
        {   // stage K/V chunk as tf32
            const float4* kg = (const float4*)(base + (size_t)kt * 64 * 128);
            float4* ks4 = (float4*)ks;
            for (int i = tid; i < 2048; i += 128) {
                int row = i >> 5, c = i & 31;
                float4 v = kg[row * 32 + c];
                v.x = __uint_as_float(tf32of(v.x));
                v.y = __uint_as_float(tf32of(v.y));
                v.z = __uint_as_float(tf32of(v.z));
                v.w = __uint_as_float(tf32of(v.w));
                ks4[row * 33 + c] = v;
            }
        }
        __syncthreads();

        // phase 1: S(16x64) = Q @ K^T
        float s[8][4];
#pragma unroll
        for (int n = 0; n < 8; n++) { s[n][0]=0.f; s[n][1]=0.f; s[n][2]=0.f; s[n][3]=0.f; }
#pragma unroll
        for (int kk = 0; kk < 16; kk++) {
            unsigned a[4];
            int cc = kk * 8 + tig;
            a[0] = qsu[(wr + gid)     * 132 + cc];
            a[1] = qsu[(wr + gid + 8) * 132 + cc];
            a[2] = qsu[(wr + gid)     * 132 + cc + 4];
            a[3] = qsu[(wr + gid + 8) * 132 + cc + 4];
#pragma unroll
            for (int n = 0; n < 8; n++) {
                unsigned b0 = ksu[(n * 8 + gid) * 132 + cc];
                unsigned b1 = ksu[(n * 8 + gid) * 132 + cc + 4];
                mma_tf32(s[n], a, b0, b1);
            }
        }

        // online softmax
        float vm0 = -1e30f, vm1 = -1e30f;
#pragma unroll
        for (int n = 0; n < 8; n++) {
            vm0 = fmaxf(vm0, fmaxf(s[n][0], s[n][1]));
            vm1 = fmaxf(vm1, fmaxf(s[n][2], s[n][3]));
        }
        vm0 = fmaxf(vm0, __shfl_xor_sync(0xffffffffu, vm0, 1));
        vm0 = fmaxf(vm0, __shfl_xor_sync(0xffffffffu, vm0, 2));
        vm1 = fmaxf(vm1, __shfl_xor_sync(0xffffffffu, vm1, 1));
        vm1 = fmaxf(vm1, __shfl_xor_sync(0xffffffffu, vm1, 2));
        float nm0 = fmaxf(m0, vm0), nm1 = fmaxf(m1, vm1);

        float sum0 = 0.f, sum1 = 0.f;
#pragma unroll
        for (int n = 0; n < 8; n++) {
            float p0 = __expf(s[n][0] - nm0);
            float p1 = __expf(s[n][1] - nm0);
            float p2 = __expf(s[n][2] - nm1);
            float p3 = __expf(s[n][3] - nm1);
            sum0 += p0 + p1; sum1 += p2 + p3;
            float* pp = ps + (wr + gid) * 68 + n * 8 + 2 * tig;
            pp[0] = __uint_as_float(tf32of(p0));
            pp[1] = __uint_as_float(tf32of(p1));
            float* pq = ps + (wr + gid + 8) * 68 + n * 8 + 2 * tig;
            pq[0] = __uint_as_float(tf32of(p2));
            pq[1] = __uint_as_float(tf32of(p3));
        }
        sum0 += __shfl_xor_sync(0xffffffffu, sum0, 1);
        sum0 += __shfl_xor_sync(0xffffffffu, sum0, 2);
        sum1 += __shfl_xor_sync(0xffffffffu, sum1, 1);
        sum1 += __shfl_xor_sync(0xffffffffu, sum1, 2);
        float alpha0 = __expf(m0 - nm0), alpha1 = __expf(m1 - nm1);
        l0 = l0 * alpha0 + sum0; m0 = nm0;
        l1 = l1 * alpha1 + sum1; m1 = nm1;
        __syncwarp();

        // phase 2: O(16x128) += P @ V
#pragma unroll
        for (int n = 0; n < 16; n++) {
            o[n][0] *= alpha0; o[n][1] *= alpha0;
            o[n][2] *= alpha1; o[n][3] *= alpha1;
        }
        const unsigned* psu = (const unsigned*)ps;
#pragma unroll
        for (int kk = 0; kk < 8; kk++) {
            unsigned pa[4];
            pa[0] = psu[(wr + gid)     * 68 + kk * 8 + tig];
            pa[1] = psu[(wr + gid + 8) * 68 + kk * 8 + tig];
            pa[2] = psu[(wr + gid)     * 68 + kk * 8 + tig + 4];
            pa[3] = psu[(wr + gid + 8) * 68 + kk * 8 + tig + 4];
#pragma unroll
            for (int n = 0; n < 16; n++) {
                unsigned b0 = ksu[(kk * 8 + tig)     * 132 + n * 8 + gid];
                unsigned b1 = ksu[(kk * 8 + tig + 4) * 132 + n * 8 + gid];
                mma_tf32(o[n], pa, b0, b1);
            }
        }
    }

    // epilogue
    float inv0 = 1.f / l0, inv1 = 1.f / l1;
    int row0 = r0 + wr + gid, row1 = row0 + 8;
    float* d0 = g_ctx + ((size_t)b * 2048 + row0) * 128;
    float* d1 = g_ctx + ((size_t)b * 2048 + row1) * 128;
#pragma unroll
    for (int n = 0; n < 16; n++) {
        int cc = n * 8 + 2 * tig;
        *(float2*)(d0 + cc) = make_float2(o[n][0] * inv0, o[n][1] * inv0);
        *(float2*)(d1 + cc) = make_float2(o[n][2] * inv1, o[n][3] * inv1);
    }
}

// ---------------- K4: concat(context, RBF kernel feature), pad to 132 ------
__global__ void k_feat(const float* __restrict__ x, const float* __restrict__ pr) {
    const int tid = threadIdx.x;
    const int warp = tid >> 5, lane = tid & 31;
    const size_t mrow = (size_t)blockIdx.x * 8 + warp;

    const float4* c4 = (const float4*)(g_ctx + mrow * 128);
    float4* o4 = (float4*)(g_ha + mrow * 132);
    o4[lane] = c4[lane];

    const float* xr = x  + mrow * 129;
    const float* pp = pr + mrow * 129;
    float ss = 0.f;
    for (int j2 = lane; j2 < 129; j2 += 32) {
        float d = xr[j2] - pp[j2];
        ss += d * d;
    }
#pragma unroll
    for (int dd = 16; dd; dd >>= 1) ss += __shfl_xor_sync(0xffffffffu, ss, dd);
    if (lane == 0)      g_ha[mrow * 132 + 128] = __expf(-ss);
    else if (lane < 4)  g_ha[mrow * 132 + 128 + lane] = 0.f;
}

// ---------------- K5: one MLP layer h = relu(h @ Wc[l]^T + bc[l]) ----------
__global__ void k_mlp(const float* __restrict__ Wc, const float* __restrict__ bc, int l) {
    extern __shared__ float sm[];
    float* Wsh  = sm;              // [132][134]
    float* insh = sm + 132 * 134;  // [64][132]
    const float* in  = (l & 1) ? g_hb : g_ha;
    float*       out = (l & 1) ? g_ha : g_hb;

    const int m0 = blockIdx.x * 64;
    const int tid = threadIdx.x;
    const float* W  = Wc + (size_t)l * 129 * 129;
    const float* bb = bc + (size_t)l * 129;

    for (int i = tid; i < 132 * 134; i += 256) {
        int r = i / 134, c = i - r * 134;
        Wsh[i] = (r < 129 && c < 129) ? W[r * 129 + c] : 0.f;
    }
    for (int i = tid; i < 64 * 132; i += 256)
        insh[i] = in[(size_t)m0 * 132 + i];
    __syncthreads();

    const int warp = tid >> 5, lane = tid & 31;
    const int rb = warp * 8;
    const u64* W2 = (const u64*)Wsh;   // row stride 67 pairs

#pragma unroll
    for (int q = 0; q < 2; q++) {
        u64 acc2[4][5] = {};
        const int r0 = rb + 4 * q;
        const u64* h0p = (const u64*)(insh + (r0 + 0) * 132);
        const u64* h1p = (const u64*)(insh + (r0 + 1) * 132);
        const u64* h2p = (const u64*)(insh + (r0 + 2) * 132);
        const u64* h3p = (const u64*)(insh + (r0 + 3) * 132);
#pragma unroll 2
        for (int jp = 0; jp < 66; jp++) {
            u64 h0 = h0p[jp], h1 = h1p[jp], h2 = h2p[jp], h3 = h3p[jp];
#pragma unroll
            for (int cg = 0; cg < 5; cg++) {
                int cc = lane + 32 * cg;
                if (cc < 132) {
                    u64 w = W2[cc * 67 + jp];
                    fma2(acc2[0][cg], h0, w); fma2(acc2[1][cg], h1, w);
                    fma2(acc2[2][cg], h2, w); fma2(acc2[3][cg], h3, w);
                }
            }
        }
#pragma unroll
        for (int cg = 0; cg < 5; cg++) {
            int cc = lane + 32 * cg;
            if (cc < 132) {
                float bv = (cc < 129) ? bb[cc] : 0.f;
#pragma unroll
                for (int i = 0; i < 4; i++)
                    out[(size_t)(m0 + rb + 4 * q + i) * 132 + cc] =
                        fmaxf(hsum2(acc2[i][cg]) + bv, 0.f);
            }
        }
    }
}

// ---------------- K6: head + log_softmax -----------------------------------
__global__ void k_head(const float* __restrict__ Wh, const float* __restrict__ bh,
                       float* __restrict__ out) {
    const int tid = threadIdx.x;
    const int warp = tid >> 5, lane = tid & 31;
    const size_t mrow = (size_t)blockIdx.x * 8 + warp;
    const float* hr = g_ha + mrow * 132;

    float s0 = 0.f, s1 = 0.f;
    for (int j2 = lane; j2 < 129; j2 += 32) {
        float hv = hr[j2];
        s0 += hv * Wh[j2];
        s1 += hv * Wh[129 + j2];
    }
#pragma unroll
    for (int dd = 16; dd; dd >>= 1) {
        s0 += __shfl_xor_sync(0xffffffffu, s0, dd);
        s1 += __shfl_xor_sync(0xffffffffu, s1, dd);
    }
    if (lane == 0) {
        s0 += bh[0]; s1 += bh[1];
        float mx = fmaxf(s0, s1);
        float lse = mx + logf(__expf(s0 - mx) + __expf(s1 - mx));
        out[2 * mrow]     = s0 - lse;
        out[2 * mrow + 1] = s1 - lse;
    }
}

// ---------------- launch ---------------------------------------------------
extern "C" void kernel_launch(void* const* d_in, const int* in_sizes, int n_in,
                              void* d_out, int out_size) {
    const float* x     = (const float*)d_in[0];
    const float* proto = (const float*)d_in[1];
    const float* Wih   = (const float*)d_in[2];
    const float* Whh   = (const float*)d_in[3];
    const float* bih   = (const float*)d_in[4];
    const float* bhh   = (const float*)d_in[5];
    const float* Wc    = (const float*)d_in[6];
    const float* bc    = (const float*)d_in[7];
    const float* Wh    = (const float*)d_in[8];
    const float* bh    = (const float*)d_in[9];
    float* out = (float*)d_out;

    const int smem_xg   = 2 * 64 * 132 * 4;                 // 67584
    const int smem_attn = (2 * 64 * 132 + 64 * 68) * 4;     // 84992
    const int smem_mlp  = (132 * 134 + 64 * 132) * 4;       // 104544

    cudaFuncSetAttribute(k_xg,   cudaFuncAttributeMaxDynamicSharedMemorySize, smem_xg);
    cudaFuncSetAttribute(k_attn, cudaFuncAttributeMaxDynamicSharedMemorySize, smem_attn);
    cudaFuncSetAttribute(k_mlp,  cudaFuncAttributeMaxDynamicSharedMemorySize, smem_mlp);

    k_xg  <<<dim3(512, 8), 256, smem_xg>>>(x, Wih, bih);
    k_nop <<<1, 32>>>();          // shift ncu slot:
    k_nop <<<1, 32>>>();          // ... so launch #4 is k_lstm3
    k_lstm3<<<32, 256>>>(Whh, bhh);   // 16 clusters of 2 CTAs
    k_attn<<<dim3(32, 16), 128, smem_attn>>>();
    k_feat<<<4096,         256>>>(x, proto);
    for (int l = 0; l < 4; l++)
        k_mlp<<<512, 256, smem_mlp>>>(Wc, bc, l);
    k_head<<<4096, 256>>>(Wh, bh, out);
}